// round 4
// baseline (speedup 1.0000x reference)
#include <cuda_runtime.h>
#include <cuda_bf16.h>
#include <math.h>
#include <stdint.h>

#define NN 100000
#define EE 1600000
#define HH 128
#define CC 64
#define SCAN_BLOCKS 98   // ceil(100000/1024)

// ---------------- scratch (device globals; no allocation allowed) ----------------
__device__ float g_pre [(size_t)NN * HH];   // conv output (post-norm, pre-BN)
__device__ float g_h1  [(size_t)NN * HH];   // layer-1 activation (residual)
__device__ __nv_bfloat16 g_mh[(size_t)NN * HH];  // mean hi / later hfinal hi
__device__ __nv_bfloat16 g_ml[(size_t)NN * HH];  // mean lo
__device__ __nv_bfloat16 g_xh[(size_t)NN * HH];  // Xr hi (x then h1)
__device__ __nv_bfloat16 g_xl[(size_t)NN * HH];  // Xr lo
__device__ __nv_bfloat16 g_wh[4 * HH * HH + CC * HH];
__device__ __nv_bfloat16 g_wl[4 * HH * HH + CC * HH];
__device__ int   g_es[EE];
__device__ int   g_ed[EE];
__device__ int   g_csr[EE];
__device__ int   g_deg[NN];
__device__ int   g_rs[NN];
__device__ int   g_cur[NN];
__device__ int   g_bsum[SCAN_BLOCKS];
__device__ int   g_is64;
__device__ float g_colsum[HH];
__device__ float g_colsq[HH];

// ==================== warp-MMA helpers (sm_80 PTX, runs on sm_100 base) ====================
__device__ __forceinline__ uint32_t smem_u32(const void* p) {
    uint32_t a;
    asm("{ .reg .u64 t; cvta.to.shared.u64 t, %1; cvt.u32.u64 %0, t; }" : "=r"(a) : "l"(p));
    return a;
}

#define LDSM4(r0, r1, r2, r3, a) \
    asm volatile("ldmatrix.sync.aligned.m8n8.x4.shared.b16 {%0,%1,%2,%3}, [%4];" \
                 : "=r"(r0), "=r"(r1), "=r"(r2), "=r"(r3) : "r"(a))

#define MMA16816(c, a0, a1, a2, a3, b0, b1) \
    asm volatile("mma.sync.aligned.m16n8k16.row.col.f32.bf16.bf16.f32 " \
                 "{%0,%1,%2,%3},{%4,%5,%6,%7},{%8,%9},{%0,%1,%2,%3};" \
                 : "+f"((c)[0]), "+f"((c)[1]), "+f"((c)[2]), "+f"((c)[3]) \
                 : "r"(a0), "r"(a1), "r"(a2), "r"(a3), "r"(b0), "r"(b1))

// pack float4 -> bf16 hi/lo uint2 pairs
__device__ __forceinline__ void pack_hilo(float4 v, uint2& hi, uint2& lo) {
    __nv_bfloat16 h0 = __float2bfloat16(v.x), h1 = __float2bfloat16(v.y);
    __nv_bfloat16 h2 = __float2bfloat16(v.z), h3 = __float2bfloat16(v.w);
    __nv_bfloat16 l0 = __float2bfloat16(v.x - __bfloat162float(h0));
    __nv_bfloat16 l1 = __float2bfloat16(v.y - __bfloat162float(h1));
    __nv_bfloat16 l2 = __float2bfloat16(v.z - __bfloat162float(h2));
    __nv_bfloat16 l3 = __float2bfloat16(v.w - __bfloat162float(h3));
    hi.x = (uint32_t)__bfloat16_as_ushort(h0) | ((uint32_t)__bfloat16_as_ushort(h1) << 16);
    hi.y = (uint32_t)__bfloat16_as_ushort(h2) | ((uint32_t)__bfloat16_as_ushort(h3) << 16);
    lo.x = (uint32_t)__bfloat16_as_ushort(l0) | ((uint32_t)__bfloat16_as_ushort(l1) << 16);
    lo.y = (uint32_t)__bfloat16_as_ushort(l2) | ((uint32_t)__bfloat16_as_ushort(l3) << 16);
}

// ---------------- edge preprocessing ----------------
__global__ void detz_k(const int* __restrict__ ei) {
    int i = blockIdx.x * blockDim.x + threadIdx.x;
    if (i < NN) g_deg[i] = 0;
    if (i == 0) {
        int ored = ei[1] | ei[3] | ei[5] | ei[7] | ei[9] | ei[11] | ei[13] | ei[15];
        g_is64 = (ored == 0) ? 1 : 0;
    }
}

__global__ void edge_conv_k(const int* __restrict__ ei) {
    int e = blockIdx.x * blockDim.x + threadIdx.x;
    if (e >= EE) return;
    int s, d;
    if (g_is64) { s = ei[2 * e]; d = ei[2 * (EE + e)]; }
    else        { s = ei[e];     d = ei[EE + e]; }
    g_es[e] = s;
    g_ed[e] = d;
    atomicAdd(&g_deg[d], 1);
}

__global__ void scan1_k() {
    __shared__ int sh[1024];
    int tid = threadIdx.x;
    int i = blockIdx.x * 1024 + tid;
    int v = (i < NN) ? g_deg[i] : 0;
    sh[tid] = v;
    __syncthreads();
    for (int off = 1; off < 1024; off <<= 1) {
        int t = (tid >= off) ? sh[tid - off] : 0;
        __syncthreads();
        sh[tid] += t;
        __syncthreads();
    }
    if (i < NN) g_rs[i] = sh[tid] - v;
    if (tid == 1023) g_bsum[blockIdx.x] = sh[1023];
}

// scan3 with inline cross-block offset (prefix over g_bsum)
__global__ void scan3_k() {
    __shared__ int soff;
    int t = threadIdx.x;
    if (t < 32) {
        int acc = 0;
        for (int b = t; b < blockIdx.x; b += 32) acc += g_bsum[b];
#pragma unroll
        for (int o = 16; o; o >>= 1) acc += __shfl_xor_sync(0xffffffffu, acc, o);
        if (t == 0) soff = acc;
    }
    __syncthreads();
    int i = blockIdx.x * 1024 + t;
    if (i < NN) {
        int v = g_rs[i] + soff;
        g_rs[i] = v;
        g_cur[i] = v;
    }
}

__global__ void csr_fill_k() {
    int e = blockIdx.x * blockDim.x + threadIdx.x;
    if (e >= EE) return;
    int p = atomicAdd(&g_cur[g_ed[e]], 1);
    g_csr[p] = g_es[e];
}

// ---------------- weight conversion to bf16 hi+lo ----------------
__global__ void wprep_k(const float* __restrict__ W1l, const float* __restrict__ W1r,
                        const float* __restrict__ W2l, const float* __restrict__ W2r,
                        const float* __restrict__ Wout) {
    int i = blockIdx.x * blockDim.x + threadIdx.x;
    if (i >= 4 * 16384 + 8192) return;
    float v;
    if (i < 16384)      v = W1l[i];
    else if (i < 32768) v = W1r[i - 16384];
    else if (i < 49152) v = W2l[i - 32768];
    else if (i < 65536) v = W2r[i - 49152];
    else                v = Wout[i - 65536];
    __nv_bfloat16 h = __float2bfloat16(v);
    g_wh[i] = h;
    g_wl[i] = __float2bfloat16(v - __bfloat162float(h));
}

__global__ void xconv_k(const float* __restrict__ x) {
    int i4 = blockIdx.x * blockDim.x + threadIdx.x;
    if (i4 >= NN * 32) return;
    float4 v = ((const float4*)x)[i4];
    uint2 hi, lo;
    pack_hilo(v, hi, lo);
    ((uint2*)g_xh)[i4] = hi;
    ((uint2*)g_xl)[i4] = lo;
}

// ---------------- mean aggregation (warp per node, 4-way ILP) -> bf16 hi/lo ----------------
__global__ void aggregate_k(const float* __restrict__ X) {
    // fold BN-stat zeroing into the first block (runs before the GEMM's atomics)
    if (blockIdx.x == 0 && threadIdx.x < 128) {
        g_colsum[threadIdx.x] = 0.f;
        g_colsq[threadIdx.x]  = 0.f;
    }
    int warp = (blockIdx.x * blockDim.x + threadIdx.x) >> 5;
    int lane = threadIdx.x & 31;
    if (warp >= NN) return;
    int rs = g_rs[warp];
    int d  = g_deg[warp];
    const float4* X4 = (const float4*)X;
    float4 a0 = make_float4(0.f, 0.f, 0.f, 0.f), a1 = a0, a2 = a0, a3 = a0;
    for (int j0 = 0; j0 < d; j0 += 32) {
        int idx = 0;
        if (j0 + lane < d) idx = g_csr[rs + j0 + lane];
        int cnt = min(32, d - j0);
        int t = 0;
        for (; t + 4 <= cnt; t += 4) {
            int s0 = __shfl_sync(0xffffffffu, idx, t);
            int s1 = __shfl_sync(0xffffffffu, idx, t + 1);
            int s2 = __shfl_sync(0xffffffffu, idx, t + 2);
            int s3 = __shfl_sync(0xffffffffu, idx, t + 3);
            float4 v0 = X4[(size_t)s0 * 32 + lane];
            float4 v1 = X4[(size_t)s1 * 32 + lane];
            float4 v2 = X4[(size_t)s2 * 32 + lane];
            float4 v3 = X4[(size_t)s3 * 32 + lane];
            a0.x += v0.x; a0.y += v0.y; a0.z += v0.z; a0.w += v0.w;
            a1.x += v1.x; a1.y += v1.y; a1.z += v1.z; a1.w += v1.w;
            a2.x += v2.x; a2.y += v2.y; a2.z += v2.z; a2.w += v2.w;
            a3.x += v3.x; a3.y += v3.y; a3.z += v3.z; a3.w += v3.w;
        }
        for (; t < cnt; t++) {
            int s = __shfl_sync(0xffffffffu, idx, t);
            float4 v = X4[(size_t)s * 32 + lane];
            a0.x += v.x; a0.y += v.y; a0.z += v.z; a0.w += v.w;
        }
    }
    float inv = 1.0f / fmaxf((float)d, 1.0f);
    float4 m;
    m.x = (a0.x + a1.x + a2.x + a3.x) * inv;
    m.y = (a0.y + a1.y + a2.y + a3.y) * inv;
    m.z = (a0.z + a1.z + a2.z + a3.z) * inv;
    m.w = (a0.w + a1.w + a2.w + a3.w) * inv;
    uint2 hi, lo;
    pack_hilo(m, hi, lo);
    size_t o4 = (size_t)warp * 32 + lane;
    ((uint2*)g_mh)[o4] = hi;
    ((uint2*)g_ml)[o4] = lo;
}

// ---------------- SAGE GEMM via mma.sync (bias + L2 norm + fused BN stats) ----------------
// smem layout (bytes); tiles are [128][136] bf16 (272B row stride; pad keeps ldmatrix conflict-free)
#define SG_AH   0
#define SG_AL   34816
#define SG_BH   69632
#define SG_BL   104448
#define SG_BIAS 139264
#define SG_INV  139776
#define SMEM_SAGE 140288

__global__ void __launch_bounds__(256, 1)
sage_mma_gemm(const __nv_bfloat16* __restrict__ Amh, const __nv_bfloat16* __restrict__ Aml,
              const __nv_bfloat16* __restrict__ Axh, const __nv_bfloat16* __restrict__ Axl,
              const __nv_bfloat16* __restrict__ Wlh, const __nv_bfloat16* __restrict__ Wll,
              const __nv_bfloat16* __restrict__ Wrh, const __nv_bfloat16* __restrict__ Wrl,
              const float* __restrict__ bias, float* __restrict__ Out)
{
    extern __shared__ char sm[];
    uint32_t sb = smem_u32(sm);
    const int tid = threadIdx.x;
    const int lane = tid & 31;
    const int wid = tid >> 5;
    const int warp_m = wid & 3;        // 4 row-groups of 32
    const int warp_n = wid >> 2;       // 2 col-groups of 64
    const int row0 = blockIdx.x * 128;

    if (tid < 128) ((float*)(sm + SG_BIAS))[tid] = bias[tid];

    float c[2][8][4];
#pragma unroll
    for (int mi = 0; mi < 2; mi++)
#pragma unroll
        for (int nf = 0; nf < 8; nf++)
#pragma unroll
            for (int q = 0; q < 4; q++) c[mi][nf][q] = 0.f;

    const int a_r = lane & 15;
    const int a_c = (lane >> 4) << 3;
    const int b_r = (lane & 7) + ((lane >> 4) << 3);
    const int b_c = ((lane >> 3) & 1) << 3;

#pragma unroll 1
    for (int p = 0; p < 2; p++) {
        const __nv_bfloat16* Ah = p ? Axh : Amh;
        const __nv_bfloat16* Al = p ? Axl : Aml;
        const __nv_bfloat16* Bh = p ? Wrh : Wlh;
        const __nv_bfloat16* Bl = p ? Wrl : Wll;
        __syncthreads();
        const uint4 z4 = make_uint4(0u, 0u, 0u, 0u);
#pragma unroll
        for (int i = 0; i < 8; i++) {
            int idx = tid + i * 256;
            int row = idx >> 4;
            int c8 = idx & 15;
            int grow = row0 + row;
            uint4 vah = z4, val = z4;
            if (grow < NN) {
                vah = *(const uint4*)(Ah + (size_t)grow * 128 + c8 * 8);
                val = *(const uint4*)(Al + (size_t)grow * 128 + c8 * 8);
            }
            *(uint4*)(sm + SG_AH + row * 272 + c8 * 16) = vah;
            *(uint4*)(sm + SG_AL + row * 272 + c8 * 16) = val;
            uint4 vbh = *(const uint4*)(Bh + row * 128 + c8 * 8);
            uint4 vbl = *(const uint4*)(Bl + row * 128 + c8 * 8);
            *(uint4*)(sm + SG_BH + row * 272 + c8 * 16) = vbh;
            *(uint4*)(sm + SG_BL + row * 272 + c8 * 16) = vbl;
        }
        __syncthreads();

#pragma unroll
        for (int ks = 0; ks < 8; ks++) {
            const int k0 = ks * 16;
            uint32_t ah[8], al[8], bh[16], bl[16];
#pragma unroll
            for (int mi = 0; mi < 2; mi++) {
                uint32_t ad = sb + SG_AH +
                    (uint32_t)(((warp_m * 32 + mi * 16 + a_r) * 136 + k0 + a_c) * 2);
                LDSM4(ah[mi*4+0], ah[mi*4+1], ah[mi*4+2], ah[mi*4+3], ad);
                LDSM4(al[mi*4+0], al[mi*4+1], al[mi*4+2], al[mi*4+3],
                      ad + (SG_AL - SG_AH));
            }
#pragma unroll
            for (int pr = 0; pr < 4; pr++) {
                uint32_t bd = sb + SG_BH +
                    (uint32_t)(((warp_n * 64 + pr * 16 + b_r) * 136 + k0 + b_c) * 2);
                LDSM4(bh[pr*4+0], bh[pr*4+1], bh[pr*4+2], bh[pr*4+3], bd);
                LDSM4(bl[pr*4+0], bl[pr*4+1], bl[pr*4+2], bl[pr*4+3],
                      bd + (SG_BL - SG_BH));
            }
#pragma unroll
            for (int mi = 0; mi < 2; mi++)
#pragma unroll
                for (int nf = 0; nf < 8; nf++)
                    MMA16816(c[mi][nf], ah[mi*4+0], ah[mi*4+1], ah[mi*4+2], ah[mi*4+3],
                             bh[nf*2+0], bh[nf*2+1]);
#pragma unroll
            for (int mi = 0; mi < 2; mi++)
#pragma unroll
                for (int nf = 0; nf < 8; nf++)
                    MMA16816(c[mi][nf], al[mi*4+0], al[mi*4+1], al[mi*4+2], al[mi*4+3],
                             bh[nf*2+0], bh[nf*2+1]);
#pragma unroll
            for (int mi = 0; mi < 2; mi++)
#pragma unroll
                for (int nf = 0; nf < 8; nf++)
                    MMA16816(c[mi][nf], ah[mi*4+0], ah[mi*4+1], ah[mi*4+2], ah[mi*4+3],
                             bl[nf*2+0], bl[nf*2+1]);
        }
    }

    // ---- epilogue: bias -> smem, L2 norm, BN partial stats ----
    __syncthreads();
    float* yp = (float*)sm;               // [128][132] overlay on tiles
    const float* sbias = (const float*)(sm + SG_BIAS);
    const int g = lane >> 2, t2 = (lane & 3) * 2;
#pragma unroll
    for (int mi = 0; mi < 2; mi++)
#pragma unroll
        for (int nf = 0; nf < 8; nf++) {
            int ra = warp_m * 32 + mi * 16 + g;
            int col = warp_n * 64 + nf * 8 + t2;
            float b0 = sbias[col], b1 = sbias[col + 1];
            *(float2*)(yp + ra * 132 + col) =
                make_float2(c[mi][nf][0] + b0, c[mi][nf][1] + b1);
            *(float2*)(yp + (ra + 8) * 132 + col) =
                make_float2(c[mi][nf][2] + b0, c[mi][nf][3] + b1);
        }
    __syncthreads();
    float* sinv = (float*)(sm + SG_INV);
    if (tid < 128) {
        float s = 0.f;
#pragma unroll
        for (int j = 0; j < 32; j++) {
            float4 v = *(float4*)(yp + tid * 132 + j * 4);
            s = fmaf(v.x, v.x, s); s = fmaf(v.y, v.y, s);
            s = fmaf(v.z, v.z, s); s = fmaf(v.w, v.w, s);
        }
        sinv[tid] = 1.0f / fmaxf(sqrtf(s), 1e-12f);
    }
    __syncthreads();

    float cs[4] = {0.f, 0.f, 0.f, 0.f};
    float cq[4] = {0.f, 0.f, 0.f, 0.f};
#pragma unroll
    for (int rr = 0; rr < 16; rr++) {
        int row = wid * 16 + rr;
        int grow = row0 + row;
        if (grow < NN) {
            float inv = sinv[row];
            float4 y4 = *(float4*)(yp + row * 132 + lane * 4);
            y4.x *= inv; y4.y *= inv; y4.z *= inv; y4.w *= inv;
            *(float4*)(Out + (size_t)grow * 128 + lane * 4) = y4;
            cs[0] += y4.x; cs[1] += y4.y; cs[2] += y4.z; cs[3] += y4.w;
            cq[0] = fmaf(y4.x, y4.x, cq[0]); cq[1] = fmaf(y4.y, y4.y, cq[1]);
            cq[2] = fmaf(y4.z, y4.z, cq[2]); cq[3] = fmaf(y4.w, y4.w, cq[3]);
        }
    }
#pragma unroll
    for (int j = 0; j < 4; j++) {
        atomicAdd(&g_colsum[lane * 4 + j], cs[j]);
        atomicAdd(&g_colsq[lane * 4 + j], cq[j]);
    }
}

// ---------------- output GEMM via mma.sync + fused log_softmax ----------------
#define OG_AH   0
#define OG_AL   34816
#define OG_BH   69632
#define OG_BL   87040
#define OG_BIAS 104448
#define SMEM_OUT 104704

__global__ void __launch_bounds__(256, 1)
out_mma_gemm(const __nv_bfloat16* __restrict__ Ah_g, const __nv_bfloat16* __restrict__ Al_g,
             const __nv_bfloat16* __restrict__ Bh_g, const __nv_bfloat16* __restrict__ Bl_g,
             const float* __restrict__ bias, float* __restrict__ Out)
{
    extern __shared__ char sm[];
    uint32_t sb = smem_u32(sm);
    const int tid = threadIdx.x;
    const int lane = tid & 31;
    const int wid = tid >> 5;
    const int row0 = blockIdx.x * 128;

    if (tid < 64) ((float*)(sm + OG_BIAS))[tid] = bias[tid];

    const uint4 z4 = make_uint4(0u, 0u, 0u, 0u);
#pragma unroll
    for (int i = 0; i < 8; i++) {
        int idx = tid + i * 256;
        int row = idx >> 4;
        int c8 = idx & 15;
        int grow = row0 + row;
        uint4 vah = z4, val = z4;
        if (grow < NN) {
            vah = *(const uint4*)(Ah_g + (size_t)grow * 128 + c8 * 8);
            val = *(const uint4*)(Al_g + (size_t)grow * 128 + c8 * 8);
        }
        *(uint4*)(sm + OG_AH + row * 272 + c8 * 16) = vah;
        *(uint4*)(sm + OG_AL + row * 272 + c8 * 16) = val;
    }
#pragma unroll
    for (int i = 0; i < 4; i++) {
        int idx = tid + i * 256;
        int row = idx >> 4;
        int c8 = idx & 15;
        uint4 vbh = *(const uint4*)(Bh_g + row * 128 + c8 * 8);
        uint4 vbl = *(const uint4*)(Bl_g + row * 128 + c8 * 8);
        *(uint4*)(sm + OG_BH + row * 272 + c8 * 16) = vbh;
        *(uint4*)(sm + OG_BL + row * 272 + c8 * 16) = vbl;
    }
    __syncthreads();

    float c[8][4];
#pragma unroll
    for (int nf = 0; nf < 8; nf++)
#pragma unroll
        for (int q = 0; q < 4; q++) c[nf][q] = 0.f;

    const int a_r = lane & 15;
    const int a_c = (lane >> 4) << 3;
    const int b_r = (lane & 7) + ((lane >> 4) << 3);
    const int b_c = ((lane >> 3) & 1) << 3;

#pragma unroll
    for (int ks = 0; ks < 8; ks++) {
        const int k0 = ks * 16;
        uint32_t ah[4], al[4], bh[16], bl[16];
        uint32_t ad = sb + OG_AH + (uint32_t)(((wid * 16 + a_r) * 136 + k0 + a_c) * 2);
        LDSM4(ah[0], ah[1], ah[2], ah[3], ad);
        LDSM4(al[0], al[1], al[2], al[3], ad + (OG_AL - OG_AH));
#pragma unroll
        for (int pr = 0; pr < 4; pr++) {
            uint32_t bd = sb + OG_BH + (uint32_t)(((pr * 16 + b_r) * 136 + k0 + b_c) * 2);
            LDSM4(bh[pr*4+0], bh[pr*4+1], bh[pr*4+2], bh[pr*4+3], bd);
            LDSM4(bl[pr*4+0], bl[pr*4+1], bl[pr*4+2], bl[pr*4+3], bd + (OG_BL - OG_BH));
        }
#pragma unroll
        for (int nf = 0; nf < 8; nf++)
            MMA16816(c[nf], ah[0], ah[1], ah[2], ah[3], bh[nf*2+0], bh[nf*2+1]);
#pragma unroll
        for (int nf = 0; nf < 8; nf++)
            MMA16816(c[nf], al[0], al[1], al[2], al[3], bh[nf*2+0], bh[nf*2+1]);
#pragma unroll
        for (int nf = 0; nf < 8; nf++)
            MMA16816(c[nf], ah[0], ah[1], ah[2], ah[3], bl[nf*2+0], bl[nf*2+1]);
    }

    __syncthreads();
    float* yp = (float*)sm;   // [128][68] overlay
    const float* sbias = (const float*)(sm + OG_BIAS);
    const int g = lane >> 2, t2 = (lane & 3) * 2;
#pragma unroll
    for (int nf = 0; nf < 8; nf++) {
        int ra = wid * 16 + g;
        int col = nf * 8 + t2;
        float b0 = sbias[col], b1 = sbias[col + 1];
        *(float2*)(yp + ra * 68 + col) = make_float2(c[nf][0] + b0, c[nf][1] + b1);
        *(float2*)(yp + (ra + 8) * 68 + col) = make_float2(c[nf][2] + b0, c[nf][3] + b1);
    }
    __syncthreads();
    if (tid < 128) {
        float y[64];
#pragma unroll
        for (int j = 0; j < 16; j++)
            *(float4*)&y[j * 4] = *(float4*)(yp + tid * 68 + j * 4);
        float m = -1e30f;
#pragma unroll
        for (int j = 0; j < 64; j++) m = fmaxf(m, y[j]);
        float s = 0.f;
#pragma unroll
        for (int j = 0; j < 64; j++) s += expf(y[j] - m);
        float lse = m + logf(s);
#pragma unroll
        for (int j = 0; j < 16; j++) {
            float4 v = *(float4*)&y[j * 4];
            v.x -= lse; v.y -= lse; v.z -= lse; v.w -= lse;
            *(float4*)(yp + tid * 68 + j * 4) = v;
        }
    }
    __syncthreads();
#pragma unroll
    for (int rr = 0; rr < 16; rr++) {
        int row = wid * 16 + rr;
        int grow = row0 + row;
        if (grow < NN) {
            float2 v = *(float2*)(yp + row * 68 + lane * 2);
            *(float2*)(Out + (size_t)grow * 64 + lane * 2) = v;
        }
    }
}

// ---------------- batch norm apply (scale/shift recomputed per block) ----------------
__global__ void bn_apply1_k(const float* __restrict__ pre,
                            const float* __restrict__ gamma, const float* __restrict__ beta) {
    __shared__ float ssc[128], ssh[128];
    int t = threadIdx.x;
    if (t < 128) {
        float mu  = g_colsum[t] * (1.0f / NN);
        float var = g_colsq[t] * (1.0f / NN) - mu * mu;
        float sc  = gamma[t] * rsqrtf(var + 1e-5f);
        ssc[t] = sc;
        ssh[t] = beta[t] - mu * sc;
    }
    __syncthreads();
    int i4 = blockIdx.x * blockDim.x + t;
    if (i4 >= NN * 32) return;
    float4 p = ((const float4*)pre)[i4];
    int col = (i4 & 31) * 4;
    float4 v;
    v.x = fmaxf(fmaf(p.x, ssc[col + 0], ssh[col + 0]), 0.f);
    v.y = fmaxf(fmaf(p.y, ssc[col + 1], ssh[col + 1]), 0.f);
    v.z = fmaxf(fmaf(p.z, ssc[col + 2], ssh[col + 2]), 0.f);
    v.w = fmaxf(fmaf(p.w, ssc[col + 3], ssh[col + 3]), 0.f);
    ((float4*)g_h1)[i4] = v;
    uint2 hi, lo;
    pack_hilo(v, hi, lo);
    ((uint2*)g_xh)[i4] = hi;
    ((uint2*)g_xl)[i4] = lo;
}

__global__ void bn_apply2_k(const float* __restrict__ pre,
                            const float* __restrict__ gamma, const float* __restrict__ beta) {
    __shared__ float ssc[128], ssh[128];
    int t = threadIdx.x;
    if (t < 128) {
        float mu  = g_colsum[t] * (1.0f / NN);
        float var = g_colsq[t] * (1.0f / NN) - mu * mu;
        float sc  = gamma[t] * rsqrtf(var + 1e-5f);
        ssc[t] = sc;
        ssh[t] = beta[t] - mu * sc;
    }
    __syncthreads();
    int i4 = blockIdx.x * blockDim.x + t;
    if (i4 >= NN * 32) return;
    float4 p = ((const float4*)pre)[i4];
    float4 r = ((const float4*)g_h1)[i4];
    int col = (i4 & 31) * 4;
    float4 v;
    v.x = fmaxf(fmaf(p.x, ssc[col + 0], ssh[col + 0]), 0.f) + r.x;
    v.y = fmaxf(fmaf(p.y, ssc[col + 1], ssh[col + 1]), 0.f) + r.y;
    v.z = fmaxf(fmaf(p.z, ssc[col + 2], ssh[col + 2]), 0.f) + r.z;
    v.w = fmaxf(fmaf(p.w, ssc[col + 3], ssh[col + 3]), 0.f) + r.w;
    uint2 hi, lo;
    pack_hilo(v, hi, lo);
    ((uint2*)g_mh)[i4] = hi;
    ((uint2*)g_ml)[i4] = lo;
}

// ---------------- launch ----------------
extern "C" void kernel_launch(void* const* d_in, const int* in_sizes, int n_in,
                              void* d_out, int out_size) {
    const float* x    = (const float*)d_in[0];
    const int*   ei   = (const int*)  d_in[1];
    const float* W1l  = (const float*)d_in[2];
    const float* b1l  = (const float*)d_in[3];
    const float* W1r  = (const float*)d_in[4];
    const float* g1   = (const float*)d_in[5];
    const float* be1  = (const float*)d_in[6];
    const float* W2l  = (const float*)d_in[7];
    const float* b2l  = (const float*)d_in[8];
    const float* W2r  = (const float*)d_in[9];
    const float* g2   = (const float*)d_in[10];
    const float* be2  = (const float*)d_in[11];
    const float* Wout = (const float*)d_in[12];
    const float* bout = (const float*)d_in[13];
    float* out = (float*)d_out;

    float *p_pre, *p_h1;
    __nv_bfloat16 *p_mh, *p_ml, *p_xh, *p_xl, *p_wh, *p_wl;
    cudaGetSymbolAddress((void**)&p_pre, g_pre);
    cudaGetSymbolAddress((void**)&p_h1,  g_h1);
    cudaGetSymbolAddress((void**)&p_mh,  g_mh);
    cudaGetSymbolAddress((void**)&p_ml,  g_ml);
    cudaGetSymbolAddress((void**)&p_xh,  g_xh);
    cudaGetSymbolAddress((void**)&p_xl,  g_xl);
    cudaGetSymbolAddress((void**)&p_wh,  g_wh);
    cudaGetSymbolAddress((void**)&p_wl,  g_wl);

    cudaFuncSetAttribute(sage_mma_gemm, cudaFuncAttributeMaxDynamicSharedMemorySize, SMEM_SAGE);
    cudaFuncSetAttribute(out_mma_gemm,  cudaFuncAttributeMaxDynamicSharedMemorySize, SMEM_OUT);

    const int ETHREADS = 256;
    const int EGRID = (EE + ETHREADS - 1) / ETHREADS;
    const int GEMM_GRID = (NN + 127) / 128;        // 782
    const int AGG_GRID = (NN * 32 + 255) / 256;    // 12500
    const int V4_GRID = (NN * 32 + 255) / 256;     // float4 elementwise grid

    // edge preprocessing (shared by both convs). Launch order puts aggregate_k
    // at position 6 so ncu (-s 5 -c 1) profiles the suspected hotspot.
    detz_k<<<(NN + 255) / 256, 256>>>(ei);          // 1
    edge_conv_k<<<EGRID, ETHREADS>>>(ei);           // 2
    scan1_k<<<SCAN_BLOCKS, 1024>>>();               // 3
    scan3_k<<<SCAN_BLOCKS, 1024>>>();               // 4
    csr_fill_k<<<EGRID, ETHREADS>>>();              // 5

    // ---- conv1 ----
    aggregate_k<<<AGG_GRID, 256>>>(x);              // 6  (also zeroes BN stats)
    xconv_k<<<V4_GRID, 256>>>(x);                   // 7
    wprep_k<<<(4 * 16384 + 8192 + 255) / 256, 256>>>(W1l, W1r, W2l, W2r, Wout);  // 8
    sage_mma_gemm<<<GEMM_GRID, 256, SMEM_SAGE>>>(p_mh, p_ml, p_xh, p_xl,
                                                 p_wh, p_wl, p_wh + 16384, p_wl + 16384,
                                                 b1l, p_pre);                    // 9
    bn_apply1_k<<<V4_GRID, 256>>>(p_pre, g1, be1);  // 10

    // ---- conv2 (+ residual) ----
    aggregate_k<<<AGG_GRID, 256>>>(p_h1);           // 11 (also zeroes BN stats)
    sage_mma_gemm<<<GEMM_GRID, 256, SMEM_SAGE>>>(p_mh, p_ml, p_xh, p_xl,
                                                 p_wh + 32768, p_wl + 32768,
                                                 p_wh + 49152, p_wl + 49152,
                                                 b2l, p_pre);                    // 12
    bn_apply2_k<<<V4_GRID, 256>>>(p_pre, g2, be2);  // 13

    // ---- output head (fused log_softmax) ----
    out_mma_gemm<<<GEMM_GRID, 256, SMEM_OUT>>>(p_mh, p_ml,
                                               p_wh + 65536, p_wl + 65536,
                                               bout, out);                       // 14
}

// round 5
// speedup vs baseline: 1.0249x; 1.0249x over previous
#include <cuda_runtime.h>
#include <cuda_bf16.h>
#include <math.h>
#include <stdint.h>

#define NN 100000
#define EE 1600000
#define HH 128
#define CC 64
#define SCAN_BLOCKS 98   // ceil(100000/1024)

// ---------------- scratch (device globals; no allocation allowed) ----------------
__device__ float g_pre [(size_t)NN * HH];   // conv output (post-norm, pre-BN)
__device__ float g_h1  [(size_t)NN * HH];   // layer-1 activation (residual)
__device__ __nv_bfloat16 g_mh[(size_t)NN * HH];  // mean hi / later hfinal hi
__device__ __nv_bfloat16 g_ml[(size_t)NN * HH];  // mean lo
__device__ __nv_bfloat16 g_xh[(size_t)NN * HH];  // Xr hi (x then h1)
__device__ __nv_bfloat16 g_xl[(size_t)NN * HH];  // Xr lo
__device__ __nv_bfloat16 g_wh[4 * HH * HH + CC * HH];
__device__ __nv_bfloat16 g_wl[4 * HH * HH + CC * HH];
__device__ int   g_es[EE];
__device__ int   g_ed[EE];
__device__ int   g_csr[EE];
__device__ int   g_deg[NN];
__device__ int   g_rs[NN];
__device__ int   g_cur[NN];
__device__ int   g_bsum[SCAN_BLOCKS];
__device__ int   g_is64;
__device__ float g_colsum[HH];
__device__ float g_colsq[HH];

// ==================== warp-MMA helpers (sm_80 PTX, runs on sm_100 base) ====================
__device__ __forceinline__ uint32_t smem_u32(const void* p) {
    uint32_t a;
    asm("{ .reg .u64 t; cvta.to.shared.u64 t, %1; cvt.u32.u64 %0, t; }" : "=r"(a) : "l"(p));
    return a;
}

#define LDSM4(r0, r1, r2, r3, a) \
    asm volatile("ldmatrix.sync.aligned.m8n8.x4.shared.b16 {%0,%1,%2,%3}, [%4];" \
                 : "=r"(r0), "=r"(r1), "=r"(r2), "=r"(r3) : "r"(a))

#define MMA16816(c, a0, a1, a2, a3, b0, b1) \
    asm volatile("mma.sync.aligned.m16n8k16.row.col.f32.bf16.bf16.f32 " \
                 "{%0,%1,%2,%3},{%4,%5,%6,%7},{%8,%9},{%0,%1,%2,%3};" \
                 : "+f"((c)[0]), "+f"((c)[1]), "+f"((c)[2]), "+f"((c)[3]) \
                 : "r"(a0), "r"(a1), "r"(a2), "r"(a3), "r"(b0), "r"(b1))

// pack float4 -> bf16 hi/lo uint2 pairs
__device__ __forceinline__ void pack_hilo(float4 v, uint2& hi, uint2& lo) {
    __nv_bfloat16 h0 = __float2bfloat16(v.x), h1 = __float2bfloat16(v.y);
    __nv_bfloat16 h2 = __float2bfloat16(v.z), h3 = __float2bfloat16(v.w);
    __nv_bfloat16 l0 = __float2bfloat16(v.x - __bfloat162float(h0));
    __nv_bfloat16 l1 = __float2bfloat16(v.y - __bfloat162float(h1));
    __nv_bfloat16 l2 = __float2bfloat16(v.z - __bfloat162float(h2));
    __nv_bfloat16 l3 = __float2bfloat16(v.w - __bfloat162float(h3));
    hi.x = (uint32_t)__bfloat16_as_ushort(h0) | ((uint32_t)__bfloat16_as_ushort(h1) << 16);
    hi.y = (uint32_t)__bfloat16_as_ushort(h2) | ((uint32_t)__bfloat16_as_ushort(h3) << 16);
    lo.x = (uint32_t)__bfloat16_as_ushort(l0) | ((uint32_t)__bfloat16_as_ushort(l1) << 16);
    lo.y = (uint32_t)__bfloat16_as_ushort(l2) | ((uint32_t)__bfloat16_as_ushort(l3) << 16);
}

// ---------------- edge preprocessing ----------------
__global__ void detz_k(const int* __restrict__ ei) {
    int i = blockIdx.x * blockDim.x + threadIdx.x;
    if (i < NN) g_deg[i] = 0;
    if (i == 0) {
        int ored = ei[1] | ei[3] | ei[5] | ei[7] | ei[9] | ei[11] | ei[13] | ei[15];
        g_is64 = (ored == 0) ? 1 : 0;
    }
}

__global__ void edge_conv_k(const int* __restrict__ ei) {
    int e = blockIdx.x * blockDim.x + threadIdx.x;
    if (e >= EE) return;
    int s, d;
    if (g_is64) { s = ei[2 * e]; d = ei[2 * (EE + e)]; }
    else        { s = ei[e];     d = ei[EE + e]; }
    g_es[e] = s;
    g_ed[e] = d;
    atomicAdd(&g_deg[d], 1);
}

__global__ void scan1_k() {
    __shared__ int sh[1024];
    int tid = threadIdx.x;
    int i = blockIdx.x * 1024 + tid;
    int v = (i < NN) ? g_deg[i] : 0;
    sh[tid] = v;
    __syncthreads();
    for (int off = 1; off < 1024; off <<= 1) {
        int t = (tid >= off) ? sh[tid - off] : 0;
        __syncthreads();
        sh[tid] += t;
        __syncthreads();
    }
    if (i < NN) g_rs[i] = sh[tid] - v;
    if (tid == 1023) g_bsum[blockIdx.x] = sh[1023];
}

// scan3 with inline cross-block offset (prefix over g_bsum)
__global__ void scan3_k() {
    __shared__ int soff;
    int t = threadIdx.x;
    if (t < 32) {
        int acc = 0;
        for (int b = t; b < blockIdx.x; b += 32) acc += g_bsum[b];
#pragma unroll
        for (int o = 16; o; o >>= 1) acc += __shfl_xor_sync(0xffffffffu, acc, o);
        if (t == 0) soff = acc;
    }
    __syncthreads();
    int i = blockIdx.x * 1024 + t;
    if (i < NN) {
        int v = g_rs[i] + soff;
        g_rs[i] = v;
        g_cur[i] = v;
    }
}

__global__ void csr_fill_k() {
    int e = blockIdx.x * blockDim.x + threadIdx.x;
    if (e >= EE) return;
    int p = atomicAdd(&g_cur[g_ed[e]], 1);
    g_csr[p] = g_es[e];
}

// ---------------- weight conversion to bf16 hi+lo ----------------
__global__ void wprep_k(const float* __restrict__ W1l, const float* __restrict__ W1r,
                        const float* __restrict__ W2l, const float* __restrict__ W2r,
                        const float* __restrict__ Wout) {
    int i = blockIdx.x * blockDim.x + threadIdx.x;
    if (i >= 4 * 16384 + 8192) return;
    float v;
    if (i < 16384)      v = W1l[i];
    else if (i < 32768) v = W1r[i - 16384];
    else if (i < 49152) v = W2l[i - 32768];
    else if (i < 65536) v = W2r[i - 49152];
    else                v = Wout[i - 65536];
    __nv_bfloat16 h = __float2bfloat16(v);
    g_wh[i] = h;
    g_wl[i] = __float2bfloat16(v - __bfloat162float(h));
}

__global__ void xconv_k(const float* __restrict__ x) {
    int i4 = blockIdx.x * blockDim.x + threadIdx.x;
    if (i4 >= NN * 32) return;
    float4 v = ((const float4*)x)[i4];
    uint2 hi, lo;
    pack_hilo(v, hi, lo);
    ((uint2*)g_xh)[i4] = hi;
    ((uint2*)g_xl)[i4] = lo;
}

// ---------------- mean aggregation (warp per node; R3 serial loop) -> bf16 hi/lo ----------------
__global__ void aggregate_k(const float* __restrict__ X) {
    // fold BN-stat zeroing into the first block (runs before the GEMM's atomics)
    if (blockIdx.x == 0 && threadIdx.x < 128) {
        g_colsum[threadIdx.x] = 0.f;
        g_colsq[threadIdx.x]  = 0.f;
    }
    int warp = (blockIdx.x * blockDim.x + threadIdx.x) >> 5;
    int lane = threadIdx.x & 31;
    if (warp >= NN) return;
    int rs = g_rs[warp];
    int d  = g_deg[warp];
    const float4* X4 = (const float4*)X;
    float4 acc = make_float4(0.f, 0.f, 0.f, 0.f);
    for (int j0 = 0; j0 < d; j0 += 32) {
        int idx = 0;
        if (j0 + lane < d) idx = g_csr[rs + j0 + lane];
        int cnt = min(32, d - j0);
        for (int t = 0; t < cnt; t++) {
            int s = __shfl_sync(0xffffffffu, idx, t);
            float4 v = X4[(size_t)s * 32 + lane];
            acc.x += v.x; acc.y += v.y; acc.z += v.z; acc.w += v.w;
        }
    }
    float inv = 1.0f / fmaxf((float)d, 1.0f);
    float4 m = make_float4(acc.x * inv, acc.y * inv, acc.z * inv, acc.w * inv);
    uint2 hi, lo;
    pack_hilo(m, hi, lo);
    size_t o4 = (size_t)warp * 32 + lane;
    ((uint2*)g_mh)[o4] = hi;
    ((uint2*)g_ml)[o4] = lo;
}

// ---------------- SAGE GEMM via mma.sync (bias + L2 norm + fused BN stats) ----------------
// smem layout (bytes); tiles are [128][136] bf16 (272B row stride; pad keeps ldmatrix conflict-free)
#define SG_AH   0
#define SG_AL   34816
#define SG_BH   69632
#define SG_BL   104448
#define SG_BIAS 139264
#define SG_INV  139776
#define SMEM_SAGE 140288

__global__ void __launch_bounds__(256, 1)
sage_mma_gemm(const __nv_bfloat16* __restrict__ Amh, const __nv_bfloat16* __restrict__ Aml,
              const __nv_bfloat16* __restrict__ Axh, const __nv_bfloat16* __restrict__ Axl,
              const __nv_bfloat16* __restrict__ Wlh, const __nv_bfloat16* __restrict__ Wll,
              const __nv_bfloat16* __restrict__ Wrh, const __nv_bfloat16* __restrict__ Wrl,
              const float* __restrict__ bias, float* __restrict__ Out)
{
    extern __shared__ char sm[];
    uint32_t sb = smem_u32(sm);
    const int tid = threadIdx.x;
    const int lane = tid & 31;
    const int wid = tid >> 5;
    const int warp_m = wid & 3;        // 4 row-groups of 32
    const int warp_n = wid >> 2;       // 2 col-groups of 64
    const int row0 = blockIdx.x * 128;

    if (tid < 128) ((float*)(sm + SG_BIAS))[tid] = bias[tid];

    float c[2][8][4];
#pragma unroll
    for (int mi = 0; mi < 2; mi++)
#pragma unroll
        for (int nf = 0; nf < 8; nf++)
#pragma unroll
            for (int q = 0; q < 4; q++) c[mi][nf][q] = 0.f;

    const int a_r = lane & 15;
    const int a_c = (lane >> 4) << 3;
    const int b_r = (lane & 7) + ((lane >> 4) << 3);
    const int b_c = ((lane >> 3) & 1) << 3;

#pragma unroll 1
    for (int p = 0; p < 2; p++) {
        const __nv_bfloat16* Ah = p ? Axh : Amh;
        const __nv_bfloat16* Al = p ? Axl : Aml;
        const __nv_bfloat16* Bh = p ? Wrh : Wlh;
        const __nv_bfloat16* Bl = p ? Wrl : Wll;
        __syncthreads();
        const uint4 z4 = make_uint4(0u, 0u, 0u, 0u);
#pragma unroll
        for (int i = 0; i < 8; i++) {
            int idx = tid + i * 256;
            int row = idx >> 4;
            int c8 = idx & 15;
            int grow = row0 + row;
            uint4 vah = z4, val = z4;
            if (grow < NN) {
                vah = *(const uint4*)(Ah + (size_t)grow * 128 + c8 * 8);
                val = *(const uint4*)(Al + (size_t)grow * 128 + c8 * 8);
            }
            *(uint4*)(sm + SG_AH + row * 272 + c8 * 16) = vah;
            *(uint4*)(sm + SG_AL + row * 272 + c8 * 16) = val;
            uint4 vbh = *(const uint4*)(Bh + row * 128 + c8 * 8);
            uint4 vbl = *(const uint4*)(Bl + row * 128 + c8 * 8);
            *(uint4*)(sm + SG_BH + row * 272 + c8 * 16) = vbh;
            *(uint4*)(sm + SG_BL + row * 272 + c8 * 16) = vbl;
        }
        __syncthreads();

#pragma unroll
        for (int ks = 0; ks < 8; ks++) {
            const int k0 = ks * 16;
            uint32_t ah[8], al[8], bh[16], bl[16];
#pragma unroll
            for (int mi = 0; mi < 2; mi++) {
                uint32_t ad = sb + SG_AH +
                    (uint32_t)(((warp_m * 32 + mi * 16 + a_r) * 136 + k0 + a_c) * 2);
                LDSM4(ah[mi*4+0], ah[mi*4+1], ah[mi*4+2], ah[mi*4+3], ad);
                LDSM4(al[mi*4+0], al[mi*4+1], al[mi*4+2], al[mi*4+3],
                      ad + (SG_AL - SG_AH));
            }
#pragma unroll
            for (int pr = 0; pr < 4; pr++) {
                uint32_t bd = sb + SG_BH +
                    (uint32_t)(((warp_n * 64 + pr * 16 + b_r) * 136 + k0 + b_c) * 2);
                LDSM4(bh[pr*4+0], bh[pr*4+1], bh[pr*4+2], bh[pr*4+3], bd);
                LDSM4(bl[pr*4+0], bl[pr*4+1], bl[pr*4+2], bl[pr*4+3],
                      bd + (SG_BL - SG_BH));
            }
#pragma unroll
            for (int mi = 0; mi < 2; mi++)
#pragma unroll
                for (int nf = 0; nf < 8; nf++)
                    MMA16816(c[mi][nf], ah[mi*4+0], ah[mi*4+1], ah[mi*4+2], ah[mi*4+3],
                             bh[nf*2+0], bh[nf*2+1]);
#pragma unroll
            for (int mi = 0; mi < 2; mi++)
#pragma unroll
                for (int nf = 0; nf < 8; nf++)
                    MMA16816(c[mi][nf], al[mi*4+0], al[mi*4+1], al[mi*4+2], al[mi*4+3],
                             bh[nf*2+0], bh[nf*2+1]);
#pragma unroll
            for (int mi = 0; mi < 2; mi++)
#pragma unroll
                for (int nf = 0; nf < 8; nf++)
                    MMA16816(c[mi][nf], ah[mi*4+0], ah[mi*4+1], ah[mi*4+2], ah[mi*4+3],
                             bl[nf*2+0], bl[nf*2+1]);
        }
    }

    // ---- epilogue: bias -> smem, L2 norm, BN partial stats ----
    __syncthreads();
    float* yp = (float*)sm;               // [128][132] overlay on tiles
    const float* sbias = (const float*)(sm + SG_BIAS);
    const int g = lane >> 2, t2 = (lane & 3) * 2;
#pragma unroll
    for (int mi = 0; mi < 2; mi++)
#pragma unroll
        for (int nf = 0; nf < 8; nf++) {
            int ra = warp_m * 32 + mi * 16 + g;
            int col = warp_n * 64 + nf * 8 + t2;
            float b0 = sbias[col], b1 = sbias[col + 1];
            *(float2*)(yp + ra * 132 + col) =
                make_float2(c[mi][nf][0] + b0, c[mi][nf][1] + b1);
            *(float2*)(yp + (ra + 8) * 132 + col) =
                make_float2(c[mi][nf][2] + b0, c[mi][nf][3] + b1);
        }
    __syncthreads();
    float* sinv = (float*)(sm + SG_INV);
    if (tid < 128) {
        float s = 0.f;
#pragma unroll
        for (int j = 0; j < 32; j++) {
            float4 v = *(float4*)(yp + tid * 132 + j * 4);
            s = fmaf(v.x, v.x, s); s = fmaf(v.y, v.y, s);
            s = fmaf(v.z, v.z, s); s = fmaf(v.w, v.w, s);
        }
        sinv[tid] = 1.0f / fmaxf(sqrtf(s), 1e-12f);
    }
    __syncthreads();

    float cs[4] = {0.f, 0.f, 0.f, 0.f};
    float cq[4] = {0.f, 0.f, 0.f, 0.f};
#pragma unroll
    for (int rr = 0; rr < 16; rr++) {
        int row = wid * 16 + rr;
        int grow = row0 + row;
        if (grow < NN) {
            float inv = sinv[row];
            float4 y4 = *(float4*)(yp + row * 132 + lane * 4);
            y4.x *= inv; y4.y *= inv; y4.z *= inv; y4.w *= inv;
            *(float4*)(Out + (size_t)grow * 128 + lane * 4) = y4;
            cs[0] += y4.x; cs[1] += y4.y; cs[2] += y4.z; cs[3] += y4.w;
            cq[0] = fmaf(y4.x, y4.x, cq[0]); cq[1] = fmaf(y4.y, y4.y, cq[1]);
            cq[2] = fmaf(y4.z, y4.z, cq[2]); cq[3] = fmaf(y4.w, y4.w, cq[3]);
        }
    }
#pragma unroll
    for (int j = 0; j < 4; j++) {
        atomicAdd(&g_colsum[lane * 4 + j], cs[j]);
        atomicAdd(&g_colsq[lane * 4 + j], cq[j]);
    }
}

// ---------------- output GEMM via mma.sync + fused log_softmax ----------------
#define OG_AH   0
#define OG_AL   34816
#define OG_BH   69632
#define OG_BL   87040
#define OG_BIAS 104448
#define SMEM_OUT 104704

__global__ void __launch_bounds__(256, 1)
out_mma_gemm(const __nv_bfloat16* __restrict__ Ah_g, const __nv_bfloat16* __restrict__ Al_g,
             const __nv_bfloat16* __restrict__ Bh_g, const __nv_bfloat16* __restrict__ Bl_g,
             const float* __restrict__ bias, float* __restrict__ Out)
{
    extern __shared__ char sm[];
    uint32_t sb = smem_u32(sm);
    const int tid = threadIdx.x;
    const int lane = tid & 31;
    const int wid = tid >> 5;
    const int row0 = blockIdx.x * 128;

    if (tid < 64) ((float*)(sm + OG_BIAS))[tid] = bias[tid];

    const uint4 z4 = make_uint4(0u, 0u, 0u, 0u);
#pragma unroll
    for (int i = 0; i < 8; i++) {
        int idx = tid + i * 256;
        int row = idx >> 4;
        int c8 = idx & 15;
        int grow = row0 + row;
        uint4 vah = z4, val = z4;
        if (grow < NN) {
            vah = *(const uint4*)(Ah_g + (size_t)grow * 128 + c8 * 8);
            val = *(const uint4*)(Al_g + (size_t)grow * 128 + c8 * 8);
        }
        *(uint4*)(sm + OG_AH + row * 272 + c8 * 16) = vah;
        *(uint4*)(sm + OG_AL + row * 272 + c8 * 16) = val;
    }
#pragma unroll
    for (int i = 0; i < 4; i++) {
        int idx = tid + i * 256;
        int row = idx >> 4;
        int c8 = idx & 15;
        uint4 vbh = *(const uint4*)(Bh_g + row * 128 + c8 * 8);
        uint4 vbl = *(const uint4*)(Bl_g + row * 128 + c8 * 8);
        *(uint4*)(sm + OG_BH + row * 272 + c8 * 16) = vbh;
        *(uint4*)(sm + OG_BL + row * 272 + c8 * 16) = vbl;
    }
    __syncthreads();

    float c[8][4];
#pragma unroll
    for (int nf = 0; nf < 8; nf++)
#pragma unroll
        for (int q = 0; q < 4; q++) c[nf][q] = 0.f;

    const int a_r = lane & 15;
    const int a_c = (lane >> 4) << 3;
    const int b_r = (lane & 7) + ((lane >> 4) << 3);
    const int b_c = ((lane >> 3) & 1) << 3;

#pragma unroll
    for (int ks = 0; ks < 8; ks++) {
        const int k0 = ks * 16;
        uint32_t ah[4], al[4], bh[16], bl[16];
        uint32_t ad = sb + OG_AH + (uint32_t)(((wid * 16 + a_r) * 136 + k0 + a_c) * 2);
        LDSM4(ah[0], ah[1], ah[2], ah[3], ad);
        LDSM4(al[0], al[1], al[2], al[3], ad + (OG_AL - OG_AH));
#pragma unroll
        for (int pr = 0; pr < 4; pr++) {
            uint32_t bd = sb + OG_BH + (uint32_t)(((pr * 16 + b_r) * 136 + k0 + b_c) * 2);
            LDSM4(bh[pr*4+0], bh[pr*4+1], bh[pr*4+2], bh[pr*4+3], bd);
            LDSM4(bl[pr*4+0], bl[pr*4+1], bl[pr*4+2], bl[pr*4+3], bd + (OG_BL - OG_BH));
        }
#pragma unroll
        for (int nf = 0; nf < 8; nf++)
            MMA16816(c[nf], ah[0], ah[1], ah[2], ah[3], bh[nf*2+0], bh[nf*2+1]);
#pragma unroll
        for (int nf = 0; nf < 8; nf++)
            MMA16816(c[nf], al[0], al[1], al[2], al[3], bh[nf*2+0], bh[nf*2+1]);
#pragma unroll
        for (int nf = 0; nf < 8; nf++)
            MMA16816(c[nf], ah[0], ah[1], ah[2], ah[3], bl[nf*2+0], bl[nf*2+1]);
    }

    __syncthreads();
    float* yp = (float*)sm;   // [128][68] overlay
    const float* sbias = (const float*)(sm + OG_BIAS);
    const int g = lane >> 2, t2 = (lane & 3) * 2;
#pragma unroll
    for (int nf = 0; nf < 8; nf++) {
        int ra = wid * 16 + g;
        int col = nf * 8 + t2;
        float b0 = sbias[col], b1 = sbias[col + 1];
        *(float2*)(yp + ra * 68 + col) = make_float2(c[nf][0] + b0, c[nf][1] + b1);
        *(float2*)(yp + (ra + 8) * 68 + col) = make_float2(c[nf][2] + b0, c[nf][3] + b1);
    }
    __syncthreads();
    if (tid < 128) {
        float y[64];
#pragma unroll
        for (int j = 0; j < 16; j++)
            *(float4*)&y[j * 4] = *(float4*)(yp + tid * 68 + j * 4);
        float m = -1e30f;
#pragma unroll
        for (int j = 0; j < 64; j++) m = fmaxf(m, y[j]);
        float s = 0.f;
#pragma unroll
        for (int j = 0; j < 64; j++) s += expf(y[j] - m);
        float lse = m + logf(s);
#pragma unroll
        for (int j = 0; j < 16; j++) {
            float4 v = *(float4*)&y[j * 4];
            v.x -= lse; v.y -= lse; v.z -= lse; v.w -= lse;
            *(float4*)(yp + tid * 68 + j * 4) = v;
        }
    }
    __syncthreads();
#pragma unroll
    for (int rr = 0; rr < 16; rr++) {
        int row = wid * 16 + rr;
        int grow = row0 + row;
        if (grow < NN) {
            float2 v = *(float2*)(yp + row * 68 + lane * 2);
            *(float2*)(Out + (size_t)grow * 64 + lane * 2) = v;
        }
    }
}

// ---------------- batch norm apply (scale/shift recomputed per block) ----------------
__global__ void bn_apply1_k(const float* __restrict__ pre,
                            const float* __restrict__ gamma, const float* __restrict__ beta) {
    __shared__ float ssc[128], ssh[128];
    int t = threadIdx.x;
    if (t < 128) {
        float mu  = g_colsum[t] * (1.0f / NN);
        float var = g_colsq[t] * (1.0f / NN) - mu * mu;
        float sc  = gamma[t] * rsqrtf(var + 1e-5f);
        ssc[t] = sc;
        ssh[t] = beta[t] - mu * sc;
    }
    __syncthreads();
    int i4 = blockIdx.x * blockDim.x + t;
    if (i4 >= NN * 32) return;
    float4 p = ((const float4*)pre)[i4];
    int col = (i4 & 31) * 4;
    float4 v;
    v.x = fmaxf(fmaf(p.x, ssc[col + 0], ssh[col + 0]), 0.f);
    v.y = fmaxf(fmaf(p.y, ssc[col + 1], ssh[col + 1]), 0.f);
    v.z = fmaxf(fmaf(p.z, ssc[col + 2], ssh[col + 2]), 0.f);
    v.w = fmaxf(fmaf(p.w, ssc[col + 3], ssh[col + 3]), 0.f);
    ((float4*)g_h1)[i4] = v;
    uint2 hi, lo;
    pack_hilo(v, hi, lo);
    ((uint2*)g_xh)[i4] = hi;
    ((uint2*)g_xl)[i4] = lo;
}

__global__ void bn_apply2_k(const float* __restrict__ pre,
                            const float* __restrict__ gamma, const float* __restrict__ beta) {
    __shared__ float ssc[128], ssh[128];
    int t = threadIdx.x;
    if (t < 128) {
        float mu  = g_colsum[t] * (1.0f / NN);
        float var = g_colsq[t] * (1.0f / NN) - mu * mu;
        float sc  = gamma[t] * rsqrtf(var + 1e-5f);
        ssc[t] = sc;
        ssh[t] = beta[t] - mu * sc;
    }
    __syncthreads();
    int i4 = blockIdx.x * blockDim.x + t;
    if (i4 >= NN * 32) return;
    float4 p = ((const float4*)pre)[i4];
    float4 r = ((const float4*)g_h1)[i4];
    int col = (i4 & 31) * 4;
    float4 v;
    v.x = fmaxf(fmaf(p.x, ssc[col + 0], ssh[col + 0]), 0.f) + r.x;
    v.y = fmaxf(fmaf(p.y, ssc[col + 1], ssh[col + 1]), 0.f) + r.y;
    v.z = fmaxf(fmaf(p.z, ssc[col + 2], ssh[col + 2]), 0.f) + r.z;
    v.w = fmaxf(fmaf(p.w, ssc[col + 3], ssh[col + 3]), 0.f) + r.w;
    uint2 hi, lo;
    pack_hilo(v, hi, lo);
    ((uint2*)g_mh)[i4] = hi;
    ((uint2*)g_ml)[i4] = lo;
}

// ---------------- launch ----------------
extern "C" void kernel_launch(void* const* d_in, const int* in_sizes, int n_in,
                              void* d_out, int out_size) {
    const float* x    = (const float*)d_in[0];
    const int*   ei   = (const int*)  d_in[1];
    const float* W1l  = (const float*)d_in[2];
    const float* b1l  = (const float*)d_in[3];
    const float* W1r  = (const float*)d_in[4];
    const float* g1   = (const float*)d_in[5];
    const float* be1  = (const float*)d_in[6];
    const float* W2l  = (const float*)d_in[7];
    const float* b2l  = (const float*)d_in[8];
    const float* W2r  = (const float*)d_in[9];
    const float* g2   = (const float*)d_in[10];
    const float* be2  = (const float*)d_in[11];
    const float* Wout = (const float*)d_in[12];
    const float* bout = (const float*)d_in[13];
    float* out = (float*)d_out;

    float *p_pre, *p_h1;
    __nv_bfloat16 *p_mh, *p_ml, *p_xh, *p_xl, *p_wh, *p_wl;
    cudaGetSymbolAddress((void**)&p_pre, g_pre);
    cudaGetSymbolAddress((void**)&p_h1,  g_h1);
    cudaGetSymbolAddress((void**)&p_mh,  g_mh);
    cudaGetSymbolAddress((void**)&p_ml,  g_ml);
    cudaGetSymbolAddress((void**)&p_xh,  g_xh);
    cudaGetSymbolAddress((void**)&p_xl,  g_xl);
    cudaGetSymbolAddress((void**)&p_wh,  g_wh);
    cudaGetSymbolAddress((void**)&p_wl,  g_wl);

    cudaFuncSetAttribute(sage_mma_gemm, cudaFuncAttributeMaxDynamicSharedMemorySize, SMEM_SAGE);
    cudaFuncSetAttribute(out_mma_gemm,  cudaFuncAttributeMaxDynamicSharedMemorySize, SMEM_OUT);

    const int ETHREADS = 256;
    const int EGRID = (EE + ETHREADS - 1) / ETHREADS;
    const int GEMM_GRID = (NN + 127) / 128;        // 782
    const int AGG_GRID = (NN * 32 + 255) / 256;    // 12500
    const int V4_GRID = (NN * 32 + 255) / 256;     // float4 elementwise grid

    // edge preprocessing (shared by both convs)
    detz_k<<<(NN + 255) / 256, 256>>>(ei);          // 1
    edge_conv_k<<<EGRID, ETHREADS>>>(ei);           // 2
    scan1_k<<<SCAN_BLOCKS, 1024>>>();               // 3
    scan3_k<<<SCAN_BLOCKS, 1024>>>();               // 4
    csr_fill_k<<<EGRID, ETHREADS>>>();              // 5

    // ---- conv1 ----
    aggregate_k<<<AGG_GRID, 256>>>(x);              // 6  (also zeroes BN stats)
    xconv_k<<<V4_GRID, 256>>>(x);                   // 7
    wprep_k<<<(4 * 16384 + 8192 + 255) / 256, 256>>>(W1l, W1r, W2l, W2r, Wout);  // 8
    sage_mma_gemm<<<GEMM_GRID, 256, SMEM_SAGE>>>(p_mh, p_ml, p_xh, p_xl,
                                                 p_wh, p_wl, p_wh + 16384, p_wl + 16384,
                                                 b1l, p_pre);                    // 9
    bn_apply1_k<<<V4_GRID, 256>>>(p_pre, g1, be1);  // 10

    // ---- conv2 (+ residual) ----
    aggregate_k<<<AGG_GRID, 256>>>(p_h1);           // 11 (also zeroes BN stats)
    sage_mma_gemm<<<GEMM_GRID, 256, SMEM_SAGE>>>(p_mh, p_ml, p_xh, p_xl,
                                                 p_wh + 32768, p_wl + 32768,
                                                 p_wh + 49152, p_wl + 49152,
                                                 b2l, p_pre);                    // 12
    bn_apply2_k<<<V4_GRID, 256>>>(p_pre, g2, be2);  // 13

    // ---- output head (fused log_softmax) ----
    out_mma_gemm<<<GEMM_GRID, 256, SMEM_OUT>>>(p_mh, p_ml,
                                               p_wh + 65536, p_wl + 65536,
                                               bout, out);                       // 14
}